// round 9
// baseline (speedup 1.0000x reference)
#include <cuda_runtime.h>
#include <cuda_bf16.h>
#include <math.h>

// Problem constants
#define BB    128
#define KTOT  8194             // pos (2) + neg (8192)
#define NMEM  100000
#define TAU_INV 14.2857142857142857f   // 1/0.07
#define KDT_F 3.0f
#define N4    (NMEM * 32)      // float4 per mem = 3,200,000
#define SPLITS 24
#define GATHB (BB * SPLITS / 8)   // 384 gather CTAs (single wave @ occ 3)
#define NG8   1025             // ceil(KTOT/8) groups of 8 k's

// bf16 mirror in MMA A-fragment order. Row r = 512B = 64 u64:
//   [mem0 row r: 32 u64][mem1 row r: 32 u64]
// Within each half, chunk kc (16 dims) = 4 u64; u64 t of a chunk =
//   lo32 = bf16x2(d[2t], d[2t+1]), hi32 = bf16x2(d[2t+8], d[2t+9])
// so lane (gid,t) gets {a0,a2} (or {a1,a3}) in ONE 8-byte load.
__device__ unsigned long long g_mem2[(size_t)NMEM * 64];

// Per-(b,split) partials: [0..2]=cij(T,1,W) [3..5]=cji [6..8]=intra0 [9..11]=intra1
__device__ float g_part2[BB][SPLITS][12];
// Per-b specials: [a0, c0, a1, c1, ia1, ib1]
__device__ float g_spec[BB][6];
__device__ unsigned int g_ctr = 0;

__device__ __forceinline__ unsigned packbf(float x, float y) {
    __nv_bfloat162 h = __floats2bfloat162_rn(x, y);
    return *reinterpret_cast<unsigned*>(&h);
}

// ---------------------------------------------------------------------------
// Prep: one streaming pass -> fp32 copy into out (L2-bypass) + permuted bf16
// mirror (normal stores, L2-resident). Task = (row, half, chunk).
// ---------------------------------------------------------------------------
__global__ void __launch_bounds__(256)
prep_kernel(const float4* __restrict__ m0, const float4* __restrict__ m1,
            float4* __restrict__ dst)   // = out + 4
{
    const int u = blockIdx.x * blockDim.x + threadIdx.x;   // [0, NMEM*16)
    if (u >= NMEM * 16) return;
    const int r = u >> 4, h = u & 15, m = h >> 3, kc = h & 7;

    const float4* src = (m ? m1 : m0) + (size_t)r * 32 + kc * 4;
    float4 f0 = __ldcs(src);
    float4 f1 = __ldcs(src + 1);
    float4 f2 = __ldcs(src + 2);
    float4 f3 = __ldcs(src + 3);

    float4* o = dst + (size_t)m * N4 + (size_t)r * 32 + kc * 4;
    __stcs(o,     f0);
    __stcs(o + 1, f1);
    __stcs(o + 2, f2);
    __stcs(o + 3, f3);

    unsigned long long* w = g_mem2 + (size_t)r * 64 + m * 32 + kc * 4;
    w[0] = (unsigned long long)packbf(f0.x, f0.y) | ((unsigned long long)packbf(f2.x, f2.y) << 32);
    w[1] = (unsigned long long)packbf(f0.z, f0.w) | ((unsigned long long)packbf(f2.z, f2.w) << 32);
    w[2] = (unsigned long long)packbf(f1.x, f1.y) | ((unsigned long long)packbf(f3.x, f3.y) << 32);
    w[3] = (unsigned long long)packbf(f1.z, f1.w) | ((unsigned long long)packbf(f3.z, f3.w) << 32);
}

// ---------------------------------------------------------------------------
// Gather: one warp per (b, split). Each iteration = 8 k's via one
// m16n8k16 bf16 MMA chain (A rows 0-7 = mem0 of k0..k7, rows 8-15 = mem1).
// B cols = [emb0, emb1, 0,...]. C gives lane 4t all four logits of k_t.
// Last CTA does the scalar reduce + momentum update.
// ---------------------------------------------------------------------------
__global__ void __launch_bounds__(256, 3)
gather_kernel(const float* __restrict__ emb0,
              const float* __restrict__ emb1,
              const float4* __restrict__ mem0,
              const float4* __restrict__ mem1,
              const int*   __restrict__ pos_idx,
              const int*   __restrict__ neg_idx,
              float* __restrict__ out)
{
    const int tid  = threadIdx.x;
    const int lane = tid & 31;
    const int warp = tid >> 5;
    const int wg    = blockIdx.x * 8 + warp;   // 0..3071
    const int b     = wg & (BB - 1);
    const int split = wg >> 7;                 // 0..SPLITS-1
    const int gid   = lane >> 2;               // 0..7: A-row / B-col index
    const int t     = lane & 3;                // k-pair index within fragments

    // B fragments (loop-invariant): col 0 = emb0[b], col 1 = emb1[b], else 0
    unsigned bfr[8][2];
    if (gid < 2) {
        const float* e = (gid == 0 ? emb0 : emb1) + b * 128;
#pragma unroll
        for (int kc = 0; kc < 8; kc++) {
            const int d = kc * 16 + 2 * t;
            bfr[kc][0] = packbf(e[d],     e[d + 1]);
            bfr[kc][1] = packbf(e[d + 8], e[d + 9]);
        }
    } else {
#pragma unroll
        for (int kc = 0; kc < 8; kc++) { bfr[kc][0] = 0; bfr[kc][1] = 0; }
    }

    float acc[12];
#pragma unroll
    for (int q = 0; q < 12; q++) acc[q] = 0.f;

    for (int gg = split; gg < NG8; gg += SPLITS) {
        const int kbase = gg * 8;
        const int k = kbase + gid;             // this lane's gathered row
        int r = 0;
        if (k < KTOT) r = (k < 2) ? pos_idx[b*2 + k] : neg_idx[b*8192 + (k - 2)];

        const unsigned long long* R = g_mem2 + (size_t)r * 64 + t;
        unsigned long long L0[8], L1[8];
#pragma unroll
        for (int kc = 0; kc < 8; kc++) {
            L0[kc] = R[kc * 4];        // mem0 half -> {a0,a2}
            L1[kc] = R[32 + kc * 4];   // mem1 half -> {a1,a3}
        }

        float d0 = 0.f, d1 = 0.f, d2 = 0.f, d3 = 0.f;
#pragma unroll
        for (int kc = 0; kc < 8; kc++) {
            unsigned a0 = (unsigned)L0[kc], a2 = (unsigned)(L0[kc] >> 32);
            unsigned a1 = (unsigned)L1[kc], a3 = (unsigned)(L1[kc] >> 32);
            asm volatile(
                "mma.sync.aligned.m16n8k16.row.col.f32.bf16.bf16.f32 "
                "{%0,%1,%2,%3}, {%4,%5,%6,%7}, {%8,%9}, {%0,%1,%2,%3};"
                : "+f"(d0), "+f"(d1), "+f"(d2), "+f"(d3)
                : "r"(a0), "r"(a1), "r"(a2), "r"(a3),
                  "r"(bfr[kc][0]), "r"(bfr[kc][1]));
        }

        // Owner lanes (t==0) hold cols {0,1} for rows gid (mem0) and gid+8 (mem1):
        //   d0 = g0.e0 = intra0, d1 = g0.e1 = cij, d2 = g1.e0 = cji, d3 = g1.e1 = intra1
        if (t == 0) {
            const float lia = d0 * TAU_INV;
            const float la  = d1 * TAU_INV;
            const float lc  = d2 * TAU_INV;
            const float lib = d3 * TAU_INV;
            const bool vi = (k < KTOT);
            const bool vn = vi && (k >= 1);     // intra excludes k=0

            if (kbase == 0) {                   // split 0 only
                if (gid == 0) { g_spec[b][0] = la; g_spec[b][1] = lc; }
                if (gid == 1) { g_spec[b][2] = la; g_spec[b][3] = lc;
                                g_spec[b][4] = lia; g_spec[b][5] = lib; }
            }

            const float ea  = vi ? __expf(la  * (1.0f/KDT_F)) : 0.f;
            const float ec  = vi ? __expf(lc  * (1.0f/KDT_F)) : 0.f;
            const float eia = vn ? __expf(lia * (1.0f/KDT_F)) : 0.f;
            const float eib = vn ? __expf(lib * (1.0f/KDT_F)) : 0.f;
            acc[0] += ea;   acc[1] += ea*ea*ea;    acc[2] += ea*(la - lc);
            acc[3] += ec;   acc[4] += ec*ec*ec;    acc[5] += ec*(lc - la);
            acc[6] += eia;  acc[7] += eia*eia*eia; acc[8] += eia*(lia - lib);
            acc[9] += eib;  acc[10]+= eib*eib*eib; acc[11]+= eib*(lib - lia);
        }
    }

    // combine the 8 owner lanes (others hold zeros)
#pragma unroll
    for (int o = 4; o <= 16; o <<= 1)
#pragma unroll
        for (int q = 0; q < 12; q++)
            acc[q] += __shfl_xor_sync(0xffffffffu, acc[q], o);
    if (lane == 0) {
#pragma unroll
        for (int q = 0; q < 12; q++) g_part2[b][split][q] = acc[q];
    }

    // ======================= fused finalize tail =======================
    __shared__ bool s_last;
    __syncthreads();
    if (tid == 0) {
        __threadfence();
        unsigned old = atomicAdd(&g_ctr, 1u);
        s_last = (old == GATHB - 1);
    }
    __syncthreads();
    if (!s_last) return;
    __threadfence();

    // ---- scalar reduce (threads 0..127) ----
    {
        float raw[4] = {0.f, 0.f, 0.f, 0.f};
        if (tid < BB) {
            float s2[12];
#pragma unroll
            for (int q = 0; q < 12; q++) {
                float a = 0.f;
                for (int sp = 0; sp < SPLITS; sp++) a += g_part2[tid][sp][q];
                s2[q] = a;
            }
            const float sAT = s2[0],  sA  = s2[1],  w1 = s2[2];
            const float sBT = s2[3],  sB  = s2[4],  w0 = s2[5];
            const float sIaT= s2[6],  sIa = s2[7],  w3 = s2[8];
            const float sIbT= s2[9],  sIb = s2[10], w2 = s2[11];
            const float LA  = logf(sA),  LB  = logf(sB);
            const float LIa = logf(sIa), LIb = logf(sIb);
            const float a0 = g_spec[tid][0], c0 = g_spec[tid][1];
            const float a1 = g_spec[tid][2], c1 = g_spec[tid][3];
            const float ia1 = g_spec[tid][4], ib1 = g_spec[tid][5];
            raw[0] = -(ia1 - LIa) - (ib1 - LIb);                     // vcl
            raw[1] = KDT_F * (w2 / sIbT + w3 / sIaT);                // soft_vcl
            raw[2] = -(0.5f*(a0+a1) - LA) - (0.5f*(c0+c1) - LB);     // icl
            raw[3] = KDT_F * (w0 / sBT + w1 / sAT);                  // soft_icl
        }
        __shared__ float scr[8][4];
#pragma unroll
        for (int q = 0; q < 4; q++) {
            float v = raw[q];
#pragma unroll
            for (int o = 16; o; o >>= 1) v += __shfl_xor_sync(0xffffffffu, v, o);
            if (lane == 0) scr[warp][q] = v;
        }
        __syncthreads();
        if (tid == 0) {
#pragma unroll
            for (int q = 0; q < 4; q++) {
                float v = 0.f;
                for (int w = 0; w < 8; w++) v += scr[w][q];
                out[q] = v / (float)BB;
            }
        }
    }

    // ---- momentum update: 256 warp-tasks (b, net), last-wins dedup ----
    for (int task = warp; task < 256; task += 8) {
        const int bb  = task & (BB - 1);
        const int net = task >> 7;
        const int r   = pos_idx[bb * 2];
        bool owner = true;
        for (int bp = bb + 1; bp < BB; bp++)
            if (pos_idx[bp * 2] == r) { owner = false; break; }
        if (!owner) continue;

        const float4* mem  = net ? mem1 : mem0;
        const float4* embp = reinterpret_cast<const float4*>(net ? emb1 : emb0);
        float4* dst = reinterpret_cast<float4*>(out + 4) + (size_t)net * N4;

        float4 m = mem[(size_t)r * 32 + lane];
        float4 e = embp[bb * 32 + lane];
        float4 u;
        u.x = 0.5f * (m.x + e.x);   // MOM = 0.5
        u.y = 0.5f * (m.y + e.y);
        u.z = 0.5f * (m.z + e.z);
        u.w = 0.5f * (m.w + e.w);
        float s2 = u.x*u.x + u.y*u.y + u.z*u.z + u.w*u.w;
#pragma unroll
        for (int o = 16; o; o >>= 1) s2 += __shfl_xor_sync(0xffffffffu, s2, o);
        const float inv = 1.0f / sqrtf(s2);
        u.x *= inv; u.y *= inv; u.z *= inv; u.w *= inv;
        dst[(size_t)r * 32 + lane] = u;
    }

    if (tid == 0) g_ctr = 0;   // reset for next graph replay
}

// ---------------------------------------------------------------------------
extern "C" void kernel_launch(void* const* d_in, const int* in_sizes, int n_in,
                              void* d_out, int out_size)
{
    const float* emb0    = (const float*)d_in[0];
    const float* emb1    = (const float*)d_in[1];
    const float* mem0    = (const float*)d_in[2];
    const float* mem1    = (const float*)d_in[3];
    const int*   pos_idx = (const int*)  d_in[4];
    const int*   neg_idx = (const int*)  d_in[5];
    float* out = (float*)d_out;

    // out layout: [vcl, soft_vcl, icl, soft_icl, new_mem0, new_mem1]
    prep_kernel<<<(NMEM*16 + 255)/256, 256>>>((const float4*)mem0,
                                              (const float4*)mem1,
                                              (float4*)(out + 4));
    gather_kernel<<<GATHB, 256>>>(emb0, emb1,
                                  (const float4*)mem0, (const float4*)mem1,
                                  pos_idx, neg_idx, out);
}

// round 10
// speedup vs baseline: 1.0047x; 1.0047x over previous
#include <cuda_runtime.h>
#include <cuda_bf16.h>
#include <math.h>

// Problem constants
#define BB    128
#define KTOT  8194             // pos (2) + neg (8192)
#define NMEM  100000
#define TAU_INV 14.2857142857142857f   // 1/0.07
#define KDT_F 3.0f
#define N4    (NMEM * 32)      // float4 per mem = 3,200,000
#define NG8   1025             // ceil(KTOT/8) groups of 8 k's
#define SPLITS 27
#define GATHB (16 * SPLITS)    // 432 gather CTAs (8 warps each) -> single wave
#define STRIDE 272             // smem row stride: 256B row + 16B pad (conflict-free)
#define WBUF  (16 * STRIDE)    // one buffer: 16 rows = 4352 B
#define CTA_SMEM (8 * 2 * WBUF) // 8 warps x double buffer = 69632 B

// bf16 mirror, plain interleaved rows: row r = [mem0 r: 256B][mem1 r: 256B]
__device__ uint4 g_memb[(size_t)NMEM * 32];

// Per-(b,split) partials: [0..2]=cij(T,1,W) [3..5]=cji [6..8]=intra0 [9..11]=intra1
__device__ float g_part2[BB][SPLITS][12];
// Per-b specials: [a0, c0, a1, c1, ia1, ib1]
__device__ float g_spec[BB][6];
__device__ unsigned int g_ctr = 0;

__device__ __forceinline__ unsigned packbf(float x, float y) {
    __nv_bfloat162 h = __floats2bfloat162_rn(x, y);
    return *reinterpret_cast<unsigned*>(&h);
}

// ---------------------------------------------------------------------------
// Prep: streaming pass -> fp32 copy into out (L2-bypass) + bf16 mirror
// (normal stores, becomes L2-resident). Task = (row, mem, 16-dim chunk).
// ---------------------------------------------------------------------------
__global__ void __launch_bounds__(256)
prep_kernel(const float4* __restrict__ m0, const float4* __restrict__ m1,
            float4* __restrict__ dst)   // = out + 4
{
    const int u = blockIdx.x * blockDim.x + threadIdx.x;   // [0, NMEM*16)
    if (u >= NMEM * 16) return;
    const int r = u >> 4, h = u & 15, m = h >> 3, q = h & 7;

    const float4* src = (m ? m1 : m0) + (size_t)r * 32 + q * 4;
    float4 f0 = __ldcs(src), f1 = __ldcs(src + 1);
    float4 f2 = __ldcs(src + 2), f3 = __ldcs(src + 3);

    float4* o = dst + (size_t)m * N4 + (size_t)r * 32 + q * 4;
    __stcs(o, f0); __stcs(o + 1, f1); __stcs(o + 2, f2); __stcs(o + 3, f3);

    uint4 p0, p1;
    p0.x = packbf(f0.x, f0.y); p0.y = packbf(f0.z, f0.w);
    p0.z = packbf(f1.x, f1.y); p0.w = packbf(f1.z, f1.w);
    p1.x = packbf(f2.x, f2.y); p1.y = packbf(f2.z, f2.w);
    p1.z = packbf(f3.x, f3.y); p1.w = packbf(f3.z, f3.w);
    g_memb[(size_t)r * 32 + m * 16 + q * 2]     = p0;
    g_memb[(size_t)r * 32 + m * 16 + q * 2 + 1] = p1;
}

// Prefetch one 8-k group: 8 cp.async warp-instructions, each = one full
// 512B interleaved row (lanes 0-15 -> smem rows i (mem0), 16-31 -> i+8 (mem1)).
__device__ __forceinline__ void prefetch_group(
    int gg, unsigned sbuf, int b, int lane, int gid,
    const int* __restrict__ pos_idx, const int* __restrict__ neg_idx)
{
    const int k = gg * 8 + gid;
    int r = 0;
    if (k < KTOT) r = (k < 2) ? pos_idx[b*2 + k] : neg_idx[b*8192 + (k - 2)];
    const char* base = reinterpret_cast<const char*>(g_memb);
    const unsigned dlane = ((lane >> 4) * 8) * STRIDE + (lane & 15) * 16;
#pragma unroll
    for (int i = 0; i < 8; i++) {
        int ri = __shfl_sync(0xffffffffu, r, i * 4);
        const void* src = base + (size_t)ri * 512 + lane * 16;
        unsigned d = sbuf + dlane + i * STRIDE;
        asm volatile("cp.async.cg.shared.global [%0], [%1], 16;\n"
                     :: "r"(d), "l"(src));
    }
}

// ---------------------------------------------------------------------------
// Gather: one warp per (b, split); 8 k's per iteration via cp.async double
// buffer -> ldmatrix -> m16n8k16 bf16 MMA chain. Last CTA finalizes.
// ---------------------------------------------------------------------------
__global__ void __launch_bounds__(256, 3)
gather_kernel(const float* __restrict__ emb0,
              const float* __restrict__ emb1,
              const float4* __restrict__ mem0,
              const float4* __restrict__ mem1,
              const int*   __restrict__ pos_idx,
              const int*   __restrict__ neg_idx,
              float* __restrict__ out)
{
    extern __shared__ char dsm[];
    const int tid  = threadIdx.x;
    const int lane = tid & 31;
    const int warp = tid >> 5;
    const int wg    = blockIdx.x * 8 + warp;
    const int b     = wg & (BB - 1);
    const int split = wg >> 7;                 // 0..SPLITS-1
    const int gid   = lane >> 2;               // 0..7
    const int t     = lane & 3;

    const unsigned sbase =
        (unsigned)__cvta_generic_to_shared(dsm) + warp * (2 * WBUF);

    // B fragments (loop-invariant): col 0 = emb0[b], col 1 = emb1[b], else 0
    unsigned bfr[8][2];
    if (gid < 2) {
        const float* e = (gid == 0 ? emb0 : emb1) + b * 128;
#pragma unroll
        for (int kc = 0; kc < 8; kc++) {
            const int d = kc * 16 + 2 * t;
            bfr[kc][0] = packbf(e[d],     e[d + 1]);
            bfr[kc][1] = packbf(e[d + 8], e[d + 9]);
        }
    } else {
#pragma unroll
        for (int kc = 0; kc < 8; kc++) { bfr[kc][0] = 0; bfr[kc][1] = 0; }
    }

    float acc[12];
#pragma unroll
    for (int q = 0; q < 12; q++) acc[q] = 0.f;

    // ldmatrix address pattern (constant part): matrix m = lane>>3
    const unsigned arow = ((lane & 7) + ((lane >> 3) & 1) * 8) * STRIDE
                        + (lane >> 4) * 16;

    // prologue: prefetch first group into buffer 0
    prefetch_group(split, sbase, b, lane, gid, pos_idx, neg_idx);
    asm volatile("cp.async.commit_group;\n" ::: "memory");

    int it = 0;
    for (int gg = split; gg < NG8; gg += SPLITS) {
        const unsigned curbuf = sbase + (it & 1) * WBUF;
        const int ngg = gg + SPLITS;
        if (ngg < NG8)
            prefetch_group(ngg, sbase + ((it & 1) ^ 1) * WBUF,
                           b, lane, gid, pos_idx, neg_idx);
        asm volatile("cp.async.commit_group;\n" ::: "memory");
        asm volatile("cp.async.wait_group 1;\n" ::: "memory");
        __syncwarp();

        float d0 = 0.f, d1 = 0.f, d2 = 0.f, d3 = 0.f;
#pragma unroll
        for (int kc = 0; kc < 8; kc++) {
            unsigned a0, a1, a2, a3;
            unsigned addr = curbuf + arow + kc * 32;
            asm volatile(
                "ldmatrix.sync.aligned.m8n8.x4.shared.b16 {%0,%1,%2,%3}, [%4];"
                : "=r"(a0), "=r"(a1), "=r"(a2), "=r"(a3) : "r"(addr));
            asm volatile(
                "mma.sync.aligned.m16n8k16.row.col.f32.bf16.bf16.f32 "
                "{%0,%1,%2,%3}, {%4,%5,%6,%7}, {%8,%9}, {%0,%1,%2,%3};"
                : "+f"(d0), "+f"(d1), "+f"(d2), "+f"(d3)
                : "r"(a0), "r"(a1), "r"(a2), "r"(a3),
                  "r"(bfr[kc][0]), "r"(bfr[kc][1]));
        }

        // Owner lanes (t==0): d0=intra0, d1=cij, d2=cji, d3=intra1 for k=kbase+gid
        if (t == 0) {
            const int k = gg * 8 + gid;
            const float lia = d0 * TAU_INV;
            const float la  = d1 * TAU_INV;
            const float lc  = d2 * TAU_INV;
            const float lib = d3 * TAU_INV;
            const bool vi = (k < KTOT);
            const bool vn = vi && (k >= 1);     // intra excludes k=0

            if (gg == 0) {                      // split 0 only
                if (gid == 0) { g_spec[b][0] = la; g_spec[b][1] = lc; }
                if (gid == 1) { g_spec[b][2] = la; g_spec[b][3] = lc;
                                g_spec[b][4] = lia; g_spec[b][5] = lib; }
            }

            const float ea  = vi ? __expf(la  * (1.0f/KDT_F)) : 0.f;
            const float ec  = vi ? __expf(lc  * (1.0f/KDT_F)) : 0.f;
            const float eia = vn ? __expf(lia * (1.0f/KDT_F)) : 0.f;
            const float eib = vn ? __expf(lib * (1.0f/KDT_F)) : 0.f;
            acc[0] += ea;   acc[1] += ea*ea*ea;    acc[2] += ea*(la - lc);
            acc[3] += ec;   acc[4] += ec*ec*ec;    acc[5] += ec*(lc - la);
            acc[6] += eia;  acc[7] += eia*eia*eia; acc[8] += eia*(lia - lib);
            acc[9] += eib;  acc[10]+= eib*eib*eib; acc[11]+= eib*(lib - lia);
        }
        it ^= 1;
    }

    // combine the 8 owner lanes (others hold zeros)
#pragma unroll
    for (int o = 4; o <= 16; o <<= 1)
#pragma unroll
        for (int q = 0; q < 12; q++)
            acc[q] += __shfl_xor_sync(0xffffffffu, acc[q], o);
    if (lane == 0) {
#pragma unroll
        for (int q = 0; q < 12; q++) g_part2[b][split][q] = acc[q];
    }

    // ======================= fused finalize tail =======================
    __shared__ bool s_last;
    __syncthreads();
    if (tid == 0) {
        __threadfence();
        unsigned old = atomicAdd(&g_ctr, 1u);
        s_last = (old == GATHB - 1);
    }
    __syncthreads();
    if (!s_last) return;
    __threadfence();

    // ---- scalar reduce (threads 0..127) ----
    {
        float raw[4] = {0.f, 0.f, 0.f, 0.f};
        if (tid < BB) {
            float s2[12];
#pragma unroll
            for (int q = 0; q < 12; q++) {
                float a = 0.f;
                for (int sp = 0; sp < SPLITS; sp++) a += g_part2[tid][sp][q];
                s2[q] = a;
            }
            const float sAT = s2[0],  sA  = s2[1],  w1 = s2[2];
            const float sBT = s2[3],  sB  = s2[4],  w0 = s2[5];
            const float sIaT= s2[6],  sIa = s2[7],  w3 = s2[8];
            const float sIbT= s2[9],  sIb = s2[10], w2 = s2[11];
            const float LA  = logf(sA),  LB  = logf(sB);
            const float LIa = logf(sIa), LIb = logf(sIb);
            const float a0 = g_spec[tid][0], c0 = g_spec[tid][1];
            const float a1 = g_spec[tid][2], c1 = g_spec[tid][3];
            const float ia1 = g_spec[tid][4], ib1 = g_spec[tid][5];
            raw[0] = -(ia1 - LIa) - (ib1 - LIb);                     // vcl
            raw[1] = KDT_F * (w2 / sIbT + w3 / sIaT);                // soft_vcl
            raw[2] = -(0.5f*(a0+a1) - LA) - (0.5f*(c0+c1) - LB);     // icl
            raw[3] = KDT_F * (w0 / sBT + w1 / sAT);                  // soft_icl
        }
        __shared__ float scr[8][4];
#pragma unroll
        for (int q = 0; q < 4; q++) {
            float v = raw[q];
#pragma unroll
            for (int o = 16; o; o >>= 1) v += __shfl_xor_sync(0xffffffffu, v, o);
            if (lane == 0) scr[warp][q] = v;
        }
        __syncthreads();
        if (tid == 0) {
#pragma unroll
            for (int q = 0; q < 4; q++) {
                float v = 0.f;
                for (int w = 0; w < 8; w++) v += scr[w][q];
                out[q] = v / (float)BB;
            }
        }
    }

    // ---- momentum update: 256 warp-tasks (b, net), last-wins dedup ----
    for (int task = warp; task < 256; task += 8) {
        const int bb  = task & (BB - 1);
        const int net = task >> 7;
        const int r   = pos_idx[bb * 2];
        bool owner = true;
        for (int bp = bb + 1; bp < BB; bp++)
            if (pos_idx[bp * 2] == r) { owner = false; break; }
        if (!owner) continue;

        const float4* mem  = net ? mem1 : mem0;
        const float4* embp = reinterpret_cast<const float4*>(net ? emb1 : emb0);
        float4* dst = reinterpret_cast<float4*>(out + 4) + (size_t)net * N4;

        float4 m = mem[(size_t)r * 32 + lane];
        float4 e = embp[bb * 32 + lane];
        float4 u;
        u.x = 0.5f * (m.x + e.x);   // MOM = 0.5
        u.y = 0.5f * (m.y + e.y);
        u.z = 0.5f * (m.z + e.z);
        u.w = 0.5f * (m.w + e.w);
        float s2 = u.x*u.x + u.y*u.y + u.z*u.z + u.w*u.w;
#pragma unroll
        for (int o = 16; o; o >>= 1) s2 += __shfl_xor_sync(0xffffffffu, s2, o);
        const float inv = 1.0f / sqrtf(s2);
        u.x *= inv; u.y *= inv; u.z *= inv; u.w *= inv;
        dst[(size_t)r * 32 + lane] = u;
    }

    if (tid == 0) g_ctr = 0;   // reset for next graph replay
}

// ---------------------------------------------------------------------------
extern "C" void kernel_launch(void* const* d_in, const int* in_sizes, int n_in,
                              void* d_out, int out_size)
{
    const float* emb0    = (const float*)d_in[0];
    const float* emb1    = (const float*)d_in[1];
    const float* mem0    = (const float*)d_in[2];
    const float* mem1    = (const float*)d_in[3];
    const int*   pos_idx = (const int*)  d_in[4];
    const int*   neg_idx = (const int*)  d_in[5];
    float* out = (float*)d_out;

    cudaFuncSetAttribute(gather_kernel,
                         cudaFuncAttributeMaxDynamicSharedMemorySize, CTA_SMEM);

    // out layout: [vcl, soft_vcl, icl, soft_icl, new_mem0, new_mem1]
    prep_kernel<<<(NMEM*16 + 255)/256, 256>>>((const float4*)mem0,
                                              (const float4*)mem1,
                                              (float4*)(out + 4));
    gather_kernel<<<GATHB, 256, CTA_SMEM>>>(emb0, emb1,
                                            (const float4*)mem0,
                                            (const float4*)mem1,
                                            pos_idx, neg_idx, out);
}